// round 1
// baseline (speedup 1.0000x reference)
#include <cuda_runtime.h>
#include <cuda_bf16.h>
#include <cstdint>

#define NNODES 50000
#define EDGES  800000
#define DIM    128
#define HEADS  8

// ---------------- scratch (static device arrays; no allocs allowed) ----------------
__device__ int   g_is64;
__device__ int   g_dst[EDGES];
__device__ int   g_src[EDGES];
__device__ int   g_deg[NNODES];
__device__ int   g_rowoff[NNODES + 1];
__device__ int   g_cursor[NNODES];
__device__ int   g_perm[EDGES];
__device__ float g_Q[(size_t)NNODES * DIM];
__device__ float g_K[(size_t)NNODES * DIM];
__device__ float g_V[(size_t)NNODES * DIM];
__device__ float g_agg[(size_t)NNODES * DIM];

// ---------------- packed f32x2 helpers (Blackwell FFMA2 path) ----------------
__device__ __forceinline__ unsigned long long packdup(float a) {
    unsigned long long r;
    unsigned int ai = __float_as_uint(a);
    asm("mov.b64 %0, {%1, %1};" : "=l"(r) : "r"(ai));
    return r;
}
__device__ __forceinline__ void ffma2(unsigned long long& d,
                                      unsigned long long a,
                                      unsigned long long b) {
    asm("fma.rn.f32x2 %0, %1, %2, %0;" : "+l"(d) : "l"(a), "l"(b));
}
__device__ __forceinline__ void unpack2(unsigned long long v, float& lo, float& hi) {
    unsigned int l, h;
    asm("mov.b64 {%0, %1}, %2;" : "=r"(l), "=r"(h) : "l"(v));
    lo = __uint_as_float(l);
    hi = __uint_as_float(h);
}

// ---------------- edge index dtype detect + convert ----------------
__global__ void detect_kernel(const void* ei) {
    if (blockIdx.x == 0 && threadIdx.x == 0) {
        const int* w = (const int*)ei;
        int is64 = 1;
        for (int i = 0; i < 64; i++) {
            int lo = w[2 * i], hi = w[2 * i + 1];
            if (hi != 0 || lo < 0 || lo >= NNODES) { is64 = 0; break; }
        }
        g_is64 = is64;
    }
}

__global__ void convert_kernel(const void* ei) {
    int i = blockIdx.x * blockDim.x + threadIdx.x;
    if (i >= EDGES) return;
    if (g_is64) {
        const long long* p = (const long long*)ei;
        g_dst[i] = (int)p[i];
        g_src[i] = (int)p[EDGES + i];
    } else {
        const int* p = (const int*)ei;
        g_dst[i] = p[i];
        g_src[i] = p[EDGES + i];
    }
}

// ---------------- CSR build ----------------
__global__ void zero_deg_kernel() {
    int i = blockIdx.x * blockDim.x + threadIdx.x;
    if (i < NNODES) g_deg[i] = 0;
}

__global__ void hist_kernel() {
    int i = blockIdx.x * blockDim.x + threadIdx.x;
    if (i < EDGES) atomicAdd(&g_deg[g_dst[i]], 1);
}

__global__ void scan_kernel() {
    __shared__ int tsum[1024];
    const int tid = threadIdx.x;
    const int CH = (NNODES + 1023) / 1024;  // 49
    int base = tid * CH;
    int s = 0;
    for (int i = 0; i < CH; i++) {
        int idx = base + i;
        if (idx < NNODES) s += g_deg[idx];
    }
    tsum[tid] = s;
    __syncthreads();
    for (int off = 1; off < 1024; off <<= 1) {
        int v = (tid >= off) ? tsum[tid - off] : 0;
        __syncthreads();
        tsum[tid] += v;
        __syncthreads();
    }
    int run = (tid == 0) ? 0 : tsum[tid - 1];
    for (int i = 0; i < CH; i++) {
        int idx = base + i;
        if (idx < NNODES) {
            g_rowoff[idx] = run;
            g_cursor[idx] = run;
            run += g_deg[idx];
        }
    }
    if (tid == 1023) g_rowoff[NNODES] = tsum[1023];
}

__global__ void scatter_kernel() {
    int i = blockIdx.x * blockDim.x + threadIdx.x;
    if (i >= EDGES) return;
    int d = g_dst[i];
    int p = atomicAdd(&g_cursor[d], 1);
    g_perm[p] = i;
}

// ---------------- GEMM: C[M,128] = A[M,128] @ W[128,128] + bias ----------------
// Block: 256 threads, tile 128x128, K=128 fully in smem, FFMA2 inner.
#define GEMM_SMEM_BYTES (2 * 128 * 132 * 4)

__global__ __launch_bounds__(256) void gemm128(const float* __restrict__ A,
                                               const float* __restrict__ W,
                                               const float* __restrict__ bias,
                                               float* __restrict__ C, int M) {
    extern __shared__ float sm[];
    float* As = sm;               // [128][132]
    float* Ws = sm + 128 * 132;   // [128][132]
    const int tid = threadIdx.x;
    const int bm = blockIdx.x * 128;

    #pragma unroll
    for (int it = 0; it < 16; ++it) {
        int f = tid + it * 256;           // float4 index 0..4095
        int r = f >> 5;
        int c = (f & 31) << 2;
        *(float4*)(Ws + r * 132 + c) = *(const float4*)(W + r * 128 + c);
        int gr = bm + r;
        float4 a = make_float4(0.f, 0.f, 0.f, 0.f);
        if (gr < M) a = *(const float4*)(A + (size_t)gr * 128 + c);
        *(float4*)(As + r * 132 + c) = a;
    }
    __syncthreads();

    const int tx = tid & 15, ty = tid >> 4;
    const int n0 = tx * 8, m0 = ty * 8;

    unsigned long long acc[8][4];
    #pragma unroll
    for (int i = 0; i < 8; i++)
        #pragma unroll
        for (int j = 0; j < 4; j++) acc[i][j] = 0ull;

    #pragma unroll 1
    for (int k = 0; k < 128; k += 4) {
        float4 a4[8];
        #pragma unroll
        for (int i = 0; i < 8; i++)
            a4[i] = *(const float4*)(As + (m0 + i) * 132 + k);
        #pragma unroll
        for (int kk = 0; kk < 4; kk++) {
            const ulonglong2* wp = (const ulonglong2*)(Ws + (k + kk) * 132 + n0);
            ulonglong2 w01 = wp[0];
            ulonglong2 w23 = wp[1];
            #pragma unroll
            for (int i = 0; i < 8; i++) {
                float av = (kk == 0) ? a4[i].x : (kk == 1) ? a4[i].y
                          : (kk == 2) ? a4[i].z : a4[i].w;
                unsigned long long ap = packdup(av);
                ffma2(acc[i][0], ap, w01.x);
                ffma2(acc[i][1], ap, w01.y);
                ffma2(acc[i][2], ap, w23.x);
                ffma2(acc[i][3], ap, w23.y);
            }
        }
    }

    #pragma unroll
    for (int i = 0; i < 8; i++) {
        int gr = bm + m0 + i;
        if (gr >= M) continue;
        float o[8];
        #pragma unroll
        for (int j = 0; j < 4; j++) {
            float lo, hi;
            unpack2(acc[i][j], lo, hi);
            o[2 * j]     = lo + bias[n0 + 2 * j];
            o[2 * j + 1] = hi + bias[n0 + 2 * j + 1];
        }
        *(float4*)(C + (size_t)gr * 128 + n0)     = make_float4(o[0], o[1], o[2], o[3]);
        *(float4*)(C + (size_t)gr * 128 + n0 + 4) = make_float4(o[4], o[5], o[6], o[7]);
    }
}

// ---------------- per-node edge attention (one warp per node) ----------------
__global__ __launch_bounds__(256) void attn_kernel(const float* __restrict__ att_bias,
                                                   float* __restrict__ logits_out) {
    int warp = (blockIdx.x * blockDim.x + threadIdx.x) >> 5;
    if (warp >= NNODES) return;
    const int lane = threadIdx.x & 31;
    const int n = warp;
    const int beg = g_rowoff[n];
    const int end = g_rowoff[n + 1];

    float4 q = *(const float4*)(g_Q + (size_t)n * 128 + lane * 4);
    const int head = lane >> 2;
    const float scale = 0.25f;  // 1/sqrt(16)

    float m = -__int_as_float(0x7f800000);  // -inf
    float s = 0.f;
    float4 acc = make_float4(0.f, 0.f, 0.f, 0.f);

    for (int j = beg; j < end; j++) {
        int e = g_perm[j];
        int sn = g_src[e];
        float4 k4 = *(const float4*)(g_K + (size_t)sn * 128 + lane * 4);
        float4 v4 = *(const float4*)(g_V + (size_t)sn * 128 + lane * 4);
        float d = q.x * k4.x + q.y * k4.y + q.z * k4.z + q.w * k4.w;
        d += __shfl_xor_sync(0xffffffffu, d, 1);
        d += __shfl_xor_sync(0xffffffffu, d, 2);
        float logit = d * scale + __ldg(att_bias + (size_t)e * HEADS + head);
        if (logits_out != nullptr && (lane & 3) == 0)
            logits_out[(size_t)e * HEADS + head] = logit;

        float nm = fmaxf(m, logit);
        float f = __expf(m - nm);
        float ex = __expf(logit - nm);
        s = s * f + ex;
        acc.x = acc.x * f + ex * v4.x;
        acc.y = acc.y * f + ex * v4.y;
        acc.z = acc.z * f + ex * v4.z;
        acc.w = acc.w * f + ex * v4.w;
        m = nm;
    }
    float inv = (s > 0.f) ? (1.f / s) : 0.f;
    acc.x *= inv; acc.y *= inv; acc.z *= inv; acc.w *= inv;
    *(float4*)(g_agg + (size_t)n * 128 + lane * 4) = acc;
}

// ---------------- launch ----------------
extern "C" void kernel_launch(void* const* d_in, const int* in_sizes, int n_in,
                              void* d_out, int out_size) {
    const float* x        = (const float*)d_in[0];
    const void*  ei       = d_in[1];
    const float* att_bias = (const float*)d_in[2];
    const float* Wq = (const float*)d_in[3];
    const float* bq = (const float*)d_in[4];
    const float* Wk = (const float*)d_in[5];
    const float* bk = (const float*)d_in[6];
    const float* Wv = (const float*)d_in[7];
    const float* bv = (const float*)d_in[8];
    const float* Wo = (const float*)d_in[9];
    const float* bo = (const float*)d_in[10];

    float* out = (float*)d_out;
    float* logits = nullptr;
    if (out_size >= NNODES * DIM + EDGES * HEADS)
        logits = out + (size_t)NNODES * DIM;

    // scratch pointers via device symbols (compile-time addressed inside kernels)
    float* dQ; cudaGetSymbolAddress((void**)&dQ, g_Q);
    float* dK; cudaGetSymbolAddress((void**)&dK, g_K);
    float* dV; cudaGetSymbolAddress((void**)&dV, g_V);
    float* dAgg; cudaGetSymbolAddress((void**)&dAgg, g_agg);

    cudaFuncSetAttribute(gemm128, cudaFuncAttributeMaxDynamicSharedMemorySize,
                         GEMM_SMEM_BYTES);

    const int EB = (EDGES + 255) / 256;    // 3125
    const int NB = (NNODES + 255) / 256;   // 196
    const int MB = (NNODES + 127) / 128;   // 391
    const int AB = (NNODES * 32 + 255) / 256;  // 6250

    detect_kernel<<<1, 32>>>(ei);
    convert_kernel<<<EB, 256>>>(ei);
    zero_deg_kernel<<<NB, 256>>>();
    hist_kernel<<<EB, 256>>>();
    scan_kernel<<<1, 1024>>>();
    scatter_kernel<<<EB, 256>>>();

    gemm128<<<MB, 256, GEMM_SMEM_BYTES>>>(x, Wq, bq, dQ, NNODES);
    gemm128<<<MB, 256, GEMM_SMEM_BYTES>>>(x, Wk, bk, dK, NNODES);
    gemm128<<<MB, 256, GEMM_SMEM_BYTES>>>(x, Wv, bv, dV, NNODES);

    attn_kernel<<<AB, 256>>>(att_bias, logits);

    gemm128<<<MB, 256, GEMM_SMEM_BYTES>>>(dAgg, Wo, bo, out, NNODES);
}

// round 3
// speedup vs baseline: 1.0372x; 1.0372x over previous
#include <cuda_runtime.h>
#include <cuda_bf16.h>
#include <cstdint>

#define NNODES 50000
#define EDGES  800000
#define DIM    128
#define HEADS  8

// ---------------- scratch (static device arrays; no allocs allowed) ----------------
__device__ int   g_is64;
__device__ int   g_dst[EDGES];
__device__ int   g_src[EDGES];
__device__ int   g_deg[NNODES];
__device__ int   g_rowoff[NNODES + 1];
__device__ int   g_cursor[NNODES];
__device__ int   g_perm[EDGES];
__device__ int   g_psrc[EDGES];
__device__ float g_Q[(size_t)NNODES * DIM];
__device__ float g_K[(size_t)NNODES * DIM];
__device__ float g_V[(size_t)NNODES * DIM];
__device__ __nv_bfloat16 g_Xh[(size_t)NNODES * DIM];
__device__ __nv_bfloat16 g_Xl[(size_t)NNODES * DIM];
__device__ __nv_bfloat16 g_Ah[(size_t)NNODES * DIM];
__device__ __nv_bfloat16 g_Al[(size_t)NNODES * DIM];
__device__ __nv_bfloat16 g_Wth[4 * DIM * DIM];  // transposed [N][K] hi
__device__ __nv_bfloat16 g_Wtl[4 * DIM * DIM];  // transposed [N][K] lo

// ---------------- helpers ----------------
__device__ __forceinline__ uint32_t smem_u32(const void* p) {
    uint32_t a;
    asm("{ .reg .u64 t; cvta.to.shared.u64 t, %1; cvt.u32.u64 %0, t; }" : "=r"(a) : "l"(p));
    return a;
}
__device__ __forceinline__ void ldsm_x4(uint32_t* r, uint32_t addr) {
    asm volatile("ldmatrix.sync.aligned.m8n8.x4.shared.b16 {%0,%1,%2,%3}, [%4];"
                 : "=r"(r[0]), "=r"(r[1]), "=r"(r[2]), "=r"(r[3]) : "r"(addr));
}
__device__ __forceinline__ void mma16816(float* d, const uint32_t* a, const uint32_t* b) {
    asm volatile(
        "mma.sync.aligned.m16n8k16.row.col.f32.bf16.bf16.f32 "
        "{%0,%1,%2,%3}, {%4,%5,%6,%7}, {%8,%9}, {%0,%1,%2,%3};"
        : "+f"(d[0]), "+f"(d[1]), "+f"(d[2]), "+f"(d[3])
        : "r"(a[0]), "r"(a[1]), "r"(a[2]), "r"(a[3]), "r"(b[0]), "r"(b[1]));
}

// ---------------- edge index dtype detect ----------------
__global__ void detect_kernel(const void* ei) {
    if (blockIdx.x == 0 && threadIdx.x == 0) {
        const int* w = (const int*)ei;
        int is64 = 1;
        for (int i = 0; i < 64; i++) {
            int lo = w[2 * i], hi = w[2 * i + 1];
            if (hi != 0 || lo < 0 || lo >= NNODES) { is64 = 0; break; }
        }
        g_is64 = is64;
    }
}

__global__ void zero_deg_kernel() {
    int i = blockIdx.x * blockDim.x + threadIdx.x;
    if (i < NNODES) g_deg[i] = 0;
}

__global__ void convert_hist_kernel(const void* ei) {
    int i = blockIdx.x * blockDim.x + threadIdx.x;
    if (i >= EDGES) return;
    int d, s;
    if (g_is64) {
        const long long* p = (const long long*)ei;
        d = (int)p[i];
        s = (int)p[EDGES + i];
    } else {
        const int* p = (const int*)ei;
        d = p[i];
        s = p[EDGES + i];
    }
    g_dst[i] = d;
    g_src[i] = s;
    atomicAdd(&g_deg[d], 1);
}

__global__ void scan_kernel() {
    __shared__ int tsum[1024];
    const int tid = threadIdx.x;
    const int CH = (NNODES + 1023) / 1024;  // 49
    int base = tid * CH;
    int s = 0;
    for (int i = 0; i < CH; i++) {
        int idx = base + i;
        if (idx < NNODES) s += g_deg[idx];
    }
    tsum[tid] = s;
    __syncthreads();
    for (int off = 1; off < 1024; off <<= 1) {
        int v = (tid >= off) ? tsum[tid - off] : 0;
        __syncthreads();
        tsum[tid] += v;
        __syncthreads();
    }
    int run = (tid == 0) ? 0 : tsum[tid - 1];
    for (int i = 0; i < CH; i++) {
        int idx = base + i;
        if (idx < NNODES) {
            g_rowoff[idx] = run;
            g_cursor[idx] = run;
            run += g_deg[idx];
        }
    }
    if (tid == 1023) g_rowoff[NNODES] = tsum[1023];
}

__global__ void scatter_kernel() {
    int i = blockIdx.x * blockDim.x + threadIdx.x;
    if (i >= EDGES) return;
    int d = g_dst[i];
    int p = atomicAdd(&g_cursor[d], 1);
    g_perm[p] = i;
    g_psrc[p] = g_src[i];
}

// ---------------- split-bf16 conversions ----------------
__global__ void conv_x_kernel(const float* __restrict__ x) {
    int i = blockIdx.x * blockDim.x + threadIdx.x;
    if (i >= NNODES * 32) return;
    int row = i >> 5;
    int col = (i & 31) << 2;
    float4 v = *(const float4*)(x + (size_t)row * DIM + col);
    __nv_bfloat16 h[4], l[4];
    float a[4] = {v.x, v.y, v.z, v.w};
    #pragma unroll
    for (int u = 0; u < 4; u++) {
        h[u] = __float2bfloat16_rn(a[u]);
        l[u] = __float2bfloat16_rn(a[u] - __bfloat162float(h[u]));
    }
    *(unsigned long long*)(g_Xh + (size_t)row * DIM + col) = *(unsigned long long*)h;
    *(unsigned long long*)(g_Xl + (size_t)row * DIM + col) = *(unsigned long long*)l;
}

__global__ void conv_w_kernel(const float* __restrict__ W0, const float* __restrict__ W1,
                              const float* __restrict__ W2, const float* __restrict__ W3) {
    int i = blockIdx.x * blockDim.x + threadIdx.x;
    if (i >= 4 * DIM * DIM) return;
    int mat = i >> 14;
    int idx = i & 16383;
    int n = idx >> 7;
    int k = idx & 127;
    const float* W = (mat == 0) ? W0 : (mat == 1) ? W1 : (mat == 2) ? W2 : W3;
    float v = W[k * DIM + n];
    __nv_bfloat16 h = __float2bfloat16_rn(v);
    __nv_bfloat16 l = __float2bfloat16_rn(v - __bfloat162float(h));
    g_Wth[mat * DIM * DIM + idx] = h;
    g_Wtl[mat * DIM * DIM + idx] = l;
}

// ---------------- mma.sync split-bf16 GEMM ----------------
// C[w][M,128] = A @ W_w + bias_w  for w in [0,count); A staged in smem once.
// smem tiles padded to stride 136 bf16 (272B) -> conflict-free ldmatrix.
#define LDA 136
#define SZ_TILE (128 * LDA * 2)            // 34816 bytes per bf16 tile
#define OFF_AH 0
#define OFF_AL SZ_TILE
#define OFF_BH (2 * SZ_TILE)
#define OFF_BL (3 * SZ_TILE)
#define GSMEM  (4 * SZ_TILE)               // 139264

__global__ __launch_bounds__(256) void gemm_mma(
    const __nv_bfloat16* __restrict__ Ah, const __nv_bfloat16* __restrict__ Al,
    const __nv_bfloat16* __restrict__ Bh_all, const __nv_bfloat16* __restrict__ Bl_all,
    const float* __restrict__ bias0, const float* __restrict__ bias1,
    const float* __restrict__ bias2,
    float* __restrict__ C0, float* __restrict__ C1, float* __restrict__ C2,
    int count, int M) {
    extern __shared__ char sm[];
    const uint32_t sb = smem_u32(sm);
    const int tid = threadIdx.x, wid = tid >> 5, lane = tid & 31;
    const int bm = blockIdx.x * 128;

    // stage A (hi+lo) once
    #pragma unroll
    for (int it = 0; it < 16; ++it) {
        int g = tid + it * 256;            // 0..4095, 4-elem groups
        int row = g >> 5;
        int col = (g & 31) << 2;
        int gr = bm + row;
        unsigned long long ah = 0ull, al = 0ull;
        if (gr < M) {
            ah = *(const unsigned long long*)(Ah + (size_t)gr * DIM + col);
            al = *(const unsigned long long*)(Al + (size_t)gr * DIM + col);
        }
        *(unsigned long long*)(sm + OFF_AH + (row * LDA + col) * 2) = ah;
        *(unsigned long long*)(sm + OFF_AL + (row * LDA + col) * 2) = al;
    }

    const int wm = wid & 3, wn = wid >> 2;
    const int m0 = wm * 32, n0 = wn * 64;
    const int g = lane >> 2, t = lane & 3;

    // ldmatrix source addresses (loop-invariant parts)
    const int ar = lane & 15, ac = (lane >> 4) << 3;
    const int nn = (lane & 7) + ((lane >> 4) << 3);
    const int kkb = ((lane >> 3) & 1) << 3;

    for (int w = 0; w < count; w++) {
        const __nv_bfloat16* Bh = Bh_all + (size_t)w * DIM * DIM;
        const __nv_bfloat16* Bl = Bl_all + (size_t)w * DIM * DIM;
        const float* bias = (w == 0) ? bias0 : (w == 1) ? bias1 : bias2;
        float* C = (w == 0) ? C0 : (w == 1) ? C1 : C2;

        __syncthreads();   // previous iter's ldmatrix reads done before overwrite
        #pragma unroll
        for (int it = 0; it < 16; ++it) {
            int gg = tid + it * 256;
            int row = gg >> 5;
            int col = (gg & 31) << 2;
            *(unsigned long long*)(sm + OFF_BH + (row * LDA + col) * 2) =
                *(const unsigned long long*)(Bh + row * DIM + col);
            *(unsigned long long*)(sm + OFF_BL + (row * LDA + col) * 2) =
                *(const unsigned long long*)(Bl + row * DIM + col);
        }
        __syncthreads();

        float acc[2][8][4];
        #pragma unroll
        for (int mt = 0; mt < 2; mt++)
            #pragma unroll
            for (int nt = 0; nt < 8; nt++)
                #pragma unroll
                for (int u = 0; u < 4; u++) acc[mt][nt][u] = 0.f;

        #pragma unroll
        for (int k = 0; k < 8; k++) {
            const int k0 = k * 16;
            uint32_t aH[2][4], aL[2][4], bH[4][4], bL[4][4];
            #pragma unroll
            for (int mt = 0; mt < 2; mt++) {
                uint32_t off = ((m0 + mt * 16 + ar) * LDA + k0 + ac) * 2;
                ldsm_x4(aH[mt], sb + OFF_AH + off);
                ldsm_x4(aL[mt], sb + OFF_AL + off);
            }
            #pragma unroll
            for (int nb = 0; nb < 4; nb++) {
                uint32_t off = ((n0 + nb * 16 + nn) * LDA + k0 + kkb) * 2;
                ldsm_x4(bH[nb], sb + OFF_BH + off);
                ldsm_x4(bL[nb], sb + OFF_BL + off);
            }
            #pragma unroll
            for (int mt = 0; mt < 2; mt++)
                #pragma unroll
                for (int nb = 0; nb < 4; nb++) {
                    mma16816(acc[mt][2 * nb],     aH[mt], bH[nb]);
                    mma16816(acc[mt][2 * nb],     aH[mt], bL[nb]);
                    mma16816(acc[mt][2 * nb],     aL[mt], bH[nb]);
                    mma16816(acc[mt][2 * nb + 1], aH[mt], bH[nb] + 2);
                    mma16816(acc[mt][2 * nb + 1], aH[mt], bL[nb] + 2);
                    mma16816(acc[mt][2 * nb + 1], aL[mt], bH[nb] + 2);
                }
        }

        // epilogue: direct stores + bias
        #pragma unroll
        for (int mt = 0; mt < 2; mt++) {
            int r0 = bm + m0 + mt * 16 + g;
            #pragma unroll
            for (int nt = 0; nt < 8; nt++) {
                int col = n0 + nt * 8 + 2 * t;
                float bx = __ldg(bias + col), by = __ldg(bias + col + 1);
                if (r0 < M) {
                    float2 o = make_float2(acc[mt][nt][0] + bx, acc[mt][nt][1] + by);
                    *(float2*)(C + (size_t)r0 * DIM + col) = o;
                }
                if (r0 + 8 < M) {
                    float2 o = make_float2(acc[mt][nt][2] + bx, acc[mt][nt][3] + by);
                    *(float2*)(C + (size_t)(r0 + 8) * DIM + col) = o;
                }
            }
        }
    }
}

// ---------------- per-node edge attention (one warp per node) ----------------
__global__ __launch_bounds__(256) void attn_kernel(const float* __restrict__ att_bias,
                                                   float* __restrict__ logits_out) {
    int warp = (blockIdx.x * blockDim.x + threadIdx.x) >> 5;
    if (warp >= NNODES) return;
    const int lane = threadIdx.x & 31;
    const int n = warp;
    const int beg = g_rowoff[n];
    const int end = g_rowoff[n + 1];

    float4 q = *(const float4*)(g_Q + (size_t)n * DIM + lane * 4);
    const int head = lane >> 2;
    const float scale = 0.25f;  // 1/sqrt(16)

    float m = -__int_as_float(0x7f800000);
    float s = 0.f;
    float4 acc = make_float4(0.f, 0.f, 0.f, 0.f);

    int j = beg;
    int e = 0;
    float4 k4, v4;
    float ab = 0.f;
    if (j < end) {
        e = g_perm[j];
        int sn = g_psrc[j];
        k4 = *(const float4*)(g_K + (size_t)sn * DIM + lane * 4);
        v4 = *(const float4*)(g_V + (size_t)sn * DIM + lane * 4);
        ab = __ldg(att_bias + (size_t)e * HEADS + head);
    }
    while (j < end) {
        int jn = j + 1;
        int en = 0;
        float4 k4n, v4n;
        float abn = 0.f;
        if (jn < end) {
            en = g_perm[jn];
            int snn = g_psrc[jn];
            k4n = *(const float4*)(g_K + (size_t)snn * DIM + lane * 4);
            v4n = *(const float4*)(g_V + (size_t)snn * DIM + lane * 4);
            abn = __ldg(att_bias + (size_t)en * HEADS + head);
        }
        float d = q.x * k4.x + q.y * k4.y + q.z * k4.z + q.w * k4.w;
        d += __shfl_xor_sync(0xffffffffu, d, 1);
        d += __shfl_xor_sync(0xffffffffu, d, 2);
        float logit = d * scale + ab;
        if ((lane & 3) == 0)
            logits_out[(size_t)e * HEADS + head] = logit;

        float nm = fmaxf(m, logit);
        float f = __expf(m - nm);
        float ex = __expf(logit - nm);
        s = s * f + ex;
        acc.x = acc.x * f + ex * v4.x;
        acc.y = acc.y * f + ex * v4.y;
        acc.z = acc.z * f + ex * v4.z;
        acc.w = acc.w * f + ex * v4.w;
        m = nm;

        j = jn; e = en; k4 = k4n; v4 = v4n; ab = abn;
    }
    float inv = (s > 0.f) ? (1.f / s) : 0.f;
    float a[4] = {acc.x * inv, acc.y * inv, acc.z * inv, acc.w * inv};
    __nv_bfloat16 h[4], l[4];
    #pragma unroll
    for (int u = 0; u < 4; u++) {
        h[u] = __float2bfloat16_rn(a[u]);
        l[u] = __float2bfloat16_rn(a[u] - __bfloat162float(h[u]));
    }
    *(unsigned long long*)(g_Ah + (size_t)n * DIM + lane * 4) = *(unsigned long long*)h;
    *(unsigned long long*)(g_Al + (size_t)n * DIM + lane * 4) = *(unsigned long long*)l;
}

// ---------------- launch ----------------
extern "C" void kernel_launch(void* const* d_in, const int* in_sizes, int n_in,
                              void* d_out, int out_size) {
    const float* x        = (const float*)d_in[0];
    const void*  ei       = d_in[1];
    const float* att_bias = (const float*)d_in[2];
    const float* Wq = (const float*)d_in[3];
    const float* bq = (const float*)d_in[4];
    const float* Wk = (const float*)d_in[5];
    const float* bk = (const float*)d_in[6];
    const float* Wv = (const float*)d_in[7];
    const float* bv = (const float*)d_in[8];
    const float* Wo = (const float*)d_in[9];
    const float* bo = (const float*)d_in[10];

    float* out = (float*)d_out;
    float* logits = out + (size_t)NNODES * DIM;

    float* dQ; cudaGetSymbolAddress((void**)&dQ, g_Q);
    float* dK; cudaGetSymbolAddress((void**)&dK, g_K);
    float* dV; cudaGetSymbolAddress((void**)&dV, g_V);
    __nv_bfloat16* dXh; cudaGetSymbolAddress((void**)&dXh, g_Xh);
    __nv_bfloat16* dXl; cudaGetSymbolAddress((void**)&dXl, g_Xl);
    __nv_bfloat16* dAh; cudaGetSymbolAddress((void**)&dAh, g_Ah);
    __nv_bfloat16* dAl; cudaGetSymbolAddress((void**)&dAl, g_Al);
    __nv_bfloat16* dWth; cudaGetSymbolAddress((void**)&dWth, g_Wth);
    __nv_bfloat16* dWtl; cudaGetSymbolAddress((void**)&dWtl, g_Wtl);

    cudaFuncSetAttribute(gemm_mma, cudaFuncAttributeMaxDynamicSharedMemorySize, GSMEM);

    const int EB = (EDGES + 255) / 256;
    const int NB = (NNODES + 255) / 256;
    const int MB = (NNODES + 127) / 128;        // 391
    const int AB = (NNODES * 32 + 255) / 256;

    detect_kernel<<<1, 32>>>(ei);
    zero_deg_kernel<<<NB, 256>>>();
    convert_hist_kernel<<<EB, 256>>>(ei);
    scan_kernel<<<1, 1024>>>();
    scatter_kernel<<<EB, 256>>>();

    conv_x_kernel<<<(NNODES * 32 + 255) / 256, 256>>>(x);
    conv_w_kernel<<<(4 * DIM * DIM + 255) / 256, 256>>>(Wq, Wk, Wv, Wo);

    // fused Q/K/V projection
    gemm_mma<<<MB, 256, GSMEM>>>(dXh, dXl, dWth, dWtl, bq, bk, bv, dQ, dK, dV, 3, NNODES);

    attn_kernel<<<AB, 256>>>(att_bias, logits);

    // output projection (weight set 3)
    gemm_mma<<<MB, 256, GSMEM>>>(dAh, dAl, dWth + 3 * DIM * DIM, dWtl + 3 * DIM * DIM,
                                 bo, nullptr, nullptr, out, nullptr, nullptr, 1, NNODES);
}

// round 4
// speedup vs baseline: 1.8811x; 1.8137x over previous
#include <cuda_runtime.h>
#include <cuda_bf16.h>
#include <cstdint>

#define NNODES 50000
#define EDGES  800000
#define DIM    128
#define HEADS  8
#define SCAN_B 256
#define NBLK   ((NNODES + SCAN_B - 1) / SCAN_B)   // 196

// ---------------- scratch (static device arrays; no allocs allowed) ----------------
__device__ int   g_is64;
__device__ int   g_dst[EDGES];
__device__ int   g_src[EDGES];
__device__ int   g_deg[NNODES];
__device__ int   g_rowoff[NNODES + 1];
__device__ int   g_cursor[NNODES];
__device__ int   g_perm[EDGES];
__device__ int   g_psrc[EDGES];
__device__ int   g_blocksum[NBLK];
__device__ int   g_blockoff[NBLK];
__device__ float g_Q[(size_t)NNODES * DIM];
__device__ float g_K[(size_t)NNODES * DIM];
__device__ float g_V[(size_t)NNODES * DIM];
__device__ __nv_bfloat16 g_Xh[(size_t)NNODES * DIM];
__device__ __nv_bfloat16 g_Xl[(size_t)NNODES * DIM];
__device__ __nv_bfloat16 g_Ah[(size_t)NNODES * DIM];
__device__ __nv_bfloat16 g_Al[(size_t)NNODES * DIM];
__device__ __nv_bfloat16 g_Wth[4 * DIM * DIM];  // transposed [N][K] hi
__device__ __nv_bfloat16 g_Wtl[4 * DIM * DIM];  // transposed [N][K] lo

// ---------------- helpers ----------------
__device__ __forceinline__ uint32_t smem_u32(const void* p) {
    uint32_t a;
    asm("{ .reg .u64 t; cvta.to.shared.u64 t, %1; cvt.u32.u64 %0, t; }" : "=r"(a) : "l"(p));
    return a;
}
__device__ __forceinline__ void ldsm_x4(uint32_t* r, uint32_t addr) {
    asm volatile("ldmatrix.sync.aligned.m8n8.x4.shared.b16 {%0,%1,%2,%3}, [%4];"
                 : "=r"(r[0]), "=r"(r[1]), "=r"(r[2]), "=r"(r[3]) : "r"(addr));
}
__device__ __forceinline__ void mma16816(float* d, const uint32_t* a, const uint32_t* b) {
    asm volatile(
        "mma.sync.aligned.m16n8k16.row.col.f32.bf16.bf16.f32 "
        "{%0,%1,%2,%3}, {%4,%5,%6,%7}, {%8,%9}, {%0,%1,%2,%3};"
        : "+f"(d[0]), "+f"(d[1]), "+f"(d[2]), "+f"(d[3])
        : "r"(a[0]), "r"(a[1]), "r"(a[2]), "r"(a[3]), "r"(b[0]), "r"(b[1]));
}

// ---------------- edge index dtype detect ----------------
__global__ void detect_kernel(const void* ei) {
    if (blockIdx.x == 0 && threadIdx.x == 0) {
        const int* w = (const int*)ei;
        int is64 = 1;
        for (int i = 0; i < 64; i++) {
            int lo = w[2 * i], hi = w[2 * i + 1];
            if (hi != 0 || lo < 0 || lo >= NNODES) { is64 = 0; break; }
        }
        g_is64 = is64;
    }
}

__global__ void zero_deg_kernel() {
    int i = blockIdx.x * blockDim.x + threadIdx.x;
    if (i < NNODES) g_deg[i] = 0;
}

__global__ void convert_hist_kernel(const void* ei) {
    int i = blockIdx.x * blockDim.x + threadIdx.x;
    if (i >= EDGES) return;
    int d, s;
    if (g_is64) {
        const long long* p = (const long long*)ei;
        d = (int)p[i];
        s = (int)p[EDGES + i];
    } else {
        const int* p = (const int*)ei;
        d = p[i];
        s = p[EDGES + i];
    }
    g_dst[i] = d;
    g_src[i] = s;
    atomicAdd(&g_deg[d], 1);
}

// ---------------- parallel 3-phase exclusive scan of g_deg -> g_rowoff ----------------
__global__ void blocksum_kernel() {
    __shared__ int red[SCAN_B];
    int i = blockIdx.x * SCAN_B + threadIdx.x;
    int v = (i < NNODES) ? g_deg[i] : 0;
    red[threadIdx.x] = v;
    __syncthreads();
    #pragma unroll
    for (int off = SCAN_B / 2; off > 0; off >>= 1) {
        if (threadIdx.x < off) red[threadIdx.x] += red[threadIdx.x + off];
        __syncthreads();
    }
    if (threadIdx.x == 0) g_blocksum[blockIdx.x] = red[0];
}

__global__ void scanblock_kernel() {
    __shared__ int sc[SCAN_B];
    int tid = threadIdx.x;
    int v = (tid < NBLK) ? g_blocksum[tid] : 0;
    sc[tid] = v;
    __syncthreads();
    #pragma unroll
    for (int off = 1; off < SCAN_B; off <<= 1) {
        int u = (tid >= off) ? sc[tid - off] : 0;
        __syncthreads();
        sc[tid] += u;
        __syncthreads();
    }
    if (tid < NBLK) g_blockoff[tid] = sc[tid] - v;  // exclusive
    if (tid == NBLK - 1) g_rowoff[NNODES] = sc[tid];
}

__global__ void writeoff_kernel() {
    __shared__ int sc[SCAN_B];
    int tid = threadIdx.x;
    int i = blockIdx.x * SCAN_B + tid;
    int v = (i < NNODES) ? g_deg[i] : 0;
    sc[tid] = v;
    __syncthreads();
    #pragma unroll
    for (int off = 1; off < SCAN_B; off <<= 1) {
        int u = (tid >= off) ? sc[tid - off] : 0;
        __syncthreads();
        sc[tid] += u;
        __syncthreads();
    }
    if (i < NNODES) {
        int off = g_blockoff[blockIdx.x] + sc[tid] - v;  // exclusive
        g_rowoff[i] = off;
        g_cursor[i] = off;
    }
}

__global__ void scatter_kernel() {
    int i = blockIdx.x * blockDim.x + threadIdx.x;
    if (i >= EDGES) return;
    int d = g_dst[i];
    int p = atomicAdd(&g_cursor[d], 1);
    g_perm[p] = i;
    g_psrc[p] = g_src[i];
}

// ---------------- split-bf16 conversions ----------------
__global__ void conv_x_kernel(const float* __restrict__ x) {
    int i = blockIdx.x * blockDim.x + threadIdx.x;
    if (i >= NNODES * 32) return;
    int row = i >> 5;
    int col = (i & 31) << 2;
    float4 v = *(const float4*)(x + (size_t)row * DIM + col);
    __nv_bfloat16 h[4], l[4];
    float a[4] = {v.x, v.y, v.z, v.w};
    #pragma unroll
    for (int u = 0; u < 4; u++) {
        h[u] = __float2bfloat16_rn(a[u]);
        l[u] = __float2bfloat16_rn(a[u] - __bfloat162float(h[u]));
    }
    *(unsigned long long*)(g_Xh + (size_t)row * DIM + col) = *(unsigned long long*)h;
    *(unsigned long long*)(g_Xl + (size_t)row * DIM + col) = *(unsigned long long*)l;
}

__global__ void conv_w_kernel(const float* __restrict__ W0, const float* __restrict__ W1,
                              const float* __restrict__ W2, const float* __restrict__ W3) {
    int i = blockIdx.x * blockDim.x + threadIdx.x;
    if (i >= 4 * DIM * DIM) return;
    int mat = i >> 14;
    int idx = i & 16383;
    int n = idx >> 7;
    int k = idx & 127;
    const float* W = (mat == 0) ? W0 : (mat == 1) ? W1 : (mat == 2) ? W2 : W3;
    float v = W[k * DIM + n];
    __nv_bfloat16 h = __float2bfloat16_rn(v);
    __nv_bfloat16 l = __float2bfloat16_rn(v - __bfloat162float(h));
    g_Wth[mat * DIM * DIM + idx] = h;
    g_Wtl[mat * DIM * DIM + idx] = l;
}

// ---------------- mma.sync split-bf16 GEMM ----------------
#define LDA 136
#define SZ_TILE (128 * LDA * 2)
#define OFF_AH 0
#define OFF_AL SZ_TILE
#define OFF_BH (2 * SZ_TILE)
#define OFF_BL (3 * SZ_TILE)
#define GSMEM  (4 * SZ_TILE)

__global__ __launch_bounds__(256) void gemm_mma(
    const __nv_bfloat16* __restrict__ Ah, const __nv_bfloat16* __restrict__ Al,
    const __nv_bfloat16* __restrict__ Bh_all, const __nv_bfloat16* __restrict__ Bl_all,
    const float* __restrict__ bias0, const float* __restrict__ bias1,
    const float* __restrict__ bias2,
    float* __restrict__ C0, float* __restrict__ C1, float* __restrict__ C2,
    int count, int M) {
    extern __shared__ char sm[];
    const uint32_t sb = smem_u32(sm);
    const int tid = threadIdx.x, wid = tid >> 5, lane = tid & 31;
    const int bm = blockIdx.x * 128;

    #pragma unroll
    for (int it = 0; it < 16; ++it) {
        int g = tid + it * 256;
        int row = g >> 5;
        int col = (g & 31) << 2;
        int gr = bm + row;
        unsigned long long ah = 0ull, al = 0ull;
        if (gr < M) {
            ah = *(const unsigned long long*)(Ah + (size_t)gr * DIM + col);
            al = *(const unsigned long long*)(Al + (size_t)gr * DIM + col);
        }
        *(unsigned long long*)(sm + OFF_AH + (row * LDA + col) * 2) = ah;
        *(unsigned long long*)(sm + OFF_AL + (row * LDA + col) * 2) = al;
    }

    const int wm = wid & 3, wn = wid >> 2;
    const int m0 = wm * 32, n0 = wn * 64;
    const int g = lane >> 2, t = lane & 3;

    const int ar = lane & 15, ac = (lane >> 4) << 3;
    const int nn = (lane & 7) + ((lane >> 4) << 3);
    const int kkb = ((lane >> 3) & 1) << 3;

    for (int w = 0; w < count; w++) {
        const __nv_bfloat16* Bh = Bh_all + (size_t)w * DIM * DIM;
        const __nv_bfloat16* Bl = Bl_all + (size_t)w * DIM * DIM;
        const float* bias = (w == 0) ? bias0 : (w == 1) ? bias1 : bias2;
        float* C = (w == 0) ? C0 : (w == 1) ? C1 : C2;

        __syncthreads();
        #pragma unroll
        for (int it = 0; it < 16; ++it) {
            int gg = tid + it * 256;
            int row = gg >> 5;
            int col = (gg & 31) << 2;
            *(unsigned long long*)(sm + OFF_BH + (row * LDA + col) * 2) =
                *(const unsigned long long*)(Bh + row * DIM + col);
            *(unsigned long long*)(sm + OFF_BL + (row * LDA + col) * 2) =
                *(const unsigned long long*)(Bl + row * DIM + col);
        }
        __syncthreads();

        float acc[2][8][4];
        #pragma unroll
        for (int mt = 0; mt < 2; mt++)
            #pragma unroll
            for (int nt = 0; nt < 8; nt++)
                #pragma unroll
                for (int u = 0; u < 4; u++) acc[mt][nt][u] = 0.f;

        #pragma unroll
        for (int k = 0; k < 8; k++) {
            const int k0 = k * 16;
            uint32_t aH[2][4], aL[2][4], bH[4][4], bL[4][4];
            #pragma unroll
            for (int mt = 0; mt < 2; mt++) {
                uint32_t off = ((m0 + mt * 16 + ar) * LDA + k0 + ac) * 2;
                ldsm_x4(aH[mt], sb + OFF_AH + off);
                ldsm_x4(aL[mt], sb + OFF_AL + off);
            }
            #pragma unroll
            for (int nb = 0; nb < 4; nb++) {
                uint32_t off = ((n0 + nb * 16 + nn) * LDA + k0 + kkb) * 2;
                ldsm_x4(bH[nb], sb + OFF_BH + off);
                ldsm_x4(bL[nb], sb + OFF_BL + off);
            }
            #pragma unroll
            for (int mt = 0; mt < 2; mt++)
                #pragma unroll
                for (int nb = 0; nb < 4; nb++) {
                    mma16816(acc[mt][2 * nb],     aH[mt], bH[nb]);
                    mma16816(acc[mt][2 * nb],     aH[mt], bL[nb]);
                    mma16816(acc[mt][2 * nb],     aL[mt], bH[nb]);
                    mma16816(acc[mt][2 * nb + 1], aH[mt], bH[nb] + 2);
                    mma16816(acc[mt][2 * nb + 1], aH[mt], bL[nb] + 2);
                    mma16816(acc[mt][2 * nb + 1], aL[mt], bH[nb] + 2);
                }
        }

        #pragma unroll
        for (int mt = 0; mt < 2; mt++) {
            int r0 = bm + m0 + mt * 16 + g;
            #pragma unroll
            for (int nt = 0; nt < 8; nt++) {
                int col = n0 + nt * 8 + 2 * t;
                float bx = __ldg(bias + col), by = __ldg(bias + col + 1);
                if (r0 < M) {
                    float2 o = make_float2(acc[mt][nt][0] + bx, acc[mt][nt][1] + by);
                    *(float2*)(C + (size_t)r0 * DIM + col) = o;
                }
                if (r0 + 8 < M) {
                    float2 o = make_float2(acc[mt][nt][2] + bx, acc[mt][nt][3] + by);
                    *(float2*)(C + (size_t)(r0 + 8) * DIM + col) = o;
                }
            }
        }
    }
}

// ---------------- per-node edge attention (one warp per node) ----------------
__global__ __launch_bounds__(256) void attn_kernel(const float* __restrict__ att_bias,
                                                   float* __restrict__ logits_out) {
    int warp = (blockIdx.x * blockDim.x + threadIdx.x) >> 5;
    if (warp >= NNODES) return;
    const int lane = threadIdx.x & 31;
    const int n = warp;
    const int beg = g_rowoff[n];
    const int end = g_rowoff[n + 1];

    float4 q = *(const float4*)(g_Q + (size_t)n * DIM + lane * 4);
    const int head = lane >> 2;
    const float scale = 0.25f;

    float m = -__int_as_float(0x7f800000);
    float s = 0.f;
    float4 acc = make_float4(0.f, 0.f, 0.f, 0.f);

    int j = beg;
    int e = 0;
    float4 k4, v4;
    float ab = 0.f;
    if (j < end) {
        e = g_perm[j];
        int sn = g_psrc[j];
        k4 = *(const float4*)(g_K + (size_t)sn * DIM + lane * 4);
        v4 = *(const float4*)(g_V + (size_t)sn * DIM + lane * 4);
        ab = __ldg(att_bias + (size_t)e * HEADS + head);
    }
    while (j < end) {
        int jn = j + 1;
        int en = 0;
        float4 k4n, v4n;
        float abn = 0.f;
        if (jn < end) {
            en = g_perm[jn];
            int snn = g_psrc[jn];
            k4n = *(const float4*)(g_K + (size_t)snn * DIM + lane * 4);
            v4n = *(const float4*)(g_V + (size_t)snn * DIM + lane * 4);
            abn = __ldg(att_bias + (size_t)en * HEADS + head);
        }
        float d = q.x * k4.x + q.y * k4.y + q.z * k4.z + q.w * k4.w;
        d += __shfl_xor_sync(0xffffffffu, d, 1);
        d += __shfl_xor_sync(0xffffffffu, d, 2);
        float logit = d * scale + ab;
        if ((lane & 3) == 0)
            logits_out[(size_t)e * HEADS + head] = logit;

        float nm = fmaxf(m, logit);
        float f = __expf(m - nm);
        float ex = __expf(logit - nm);
        s = s * f + ex;
        acc.x = acc.x * f + ex * v4.x;
        acc.y = acc.y * f + ex * v4.y;
        acc.z = acc.z * f + ex * v4.z;
        acc.w = acc.w * f + ex * v4.w;
        m = nm;

        j = jn; e = en; k4 = k4n; v4 = v4n; ab = abn;
    }
    float inv = (s > 0.f) ? (1.f / s) : 0.f;
    float a[4] = {acc.x * inv, acc.y * inv, acc.z * inv, acc.w * inv};
    __nv_bfloat16 h[4], l[4];
    #pragma unroll
    for (int u = 0; u < 4; u++) {
        h[u] = __float2bfloat16_rn(a[u]);
        l[u] = __float2bfloat16_rn(a[u] - __bfloat162float(h[u]));
    }
    *(unsigned long long*)(g_Ah + (size_t)n * DIM + lane * 4) = *(unsigned long long*)h;
    *(unsigned long long*)(g_Al + (size_t)n * DIM + lane * 4) = *(unsigned long long*)l;
}

// ---------------- launch ----------------
extern "C" void kernel_launch(void* const* d_in, const int* in_sizes, int n_in,
                              void* d_out, int out_size) {
    const float* x        = (const float*)d_in[0];
    const void*  ei       = d_in[1];
    const float* att_bias = (const float*)d_in[2];
    const float* Wq = (const float*)d_in[3];
    const float* bq = (const float*)d_in[4];
    const float* Wk = (const float*)d_in[5];
    const float* bk = (const float*)d_in[6];
    const float* Wv = (const float*)d_in[7];
    const float* bv = (const float*)d_in[8];
    const float* Wo = (const float*)d_in[9];
    const float* bo = (const float*)d_in[10];

    float* out = (float*)d_out;
    float* logits = out + (size_t)NNODES * DIM;

    float* dQ; cudaGetSymbolAddress((void**)&dQ, g_Q);
    float* dK; cudaGetSymbolAddress((void**)&dK, g_K);
    float* dV; cudaGetSymbolAddress((void**)&dV, g_V);
    __nv_bfloat16* dXh; cudaGetSymbolAddress((void**)&dXh, g_Xh);
    __nv_bfloat16* dXl; cudaGetSymbolAddress((void**)&dXl, g_Xl);
    __nv_bfloat16* dAh; cudaGetSymbolAddress((void**)&dAh, g_Ah);
    __nv_bfloat16* dAl; cudaGetSymbolAddress((void**)&dAl, g_Al);
    __nv_bfloat16* dWth; cudaGetSymbolAddress((void**)&dWth, g_Wth);
    __nv_bfloat16* dWtl; cudaGetSymbolAddress((void**)&dWtl, g_Wtl);

    cudaFuncSetAttribute(gemm_mma, cudaFuncAttributeMaxDynamicSharedMemorySize, GSMEM);

    const int EB = (EDGES + 255) / 256;
    const int NB = (NNODES + 255) / 256;
    const int MB = (NNODES + 127) / 128;
    const int AB = (NNODES * 32 + 255) / 256;

    detect_kernel<<<1, 32>>>(ei);
    zero_deg_kernel<<<NB, 256>>>();
    convert_hist_kernel<<<EB, 256>>>(ei);
    blocksum_kernel<<<NBLK, SCAN_B>>>();
    scanblock_kernel<<<1, SCAN_B>>>();
    writeoff_kernel<<<NBLK, SCAN_B>>>();
    scatter_kernel<<<EB, 256>>>();

    conv_x_kernel<<<(NNODES * 32 + 255) / 256, 256>>>(x);
    conv_w_kernel<<<(4 * DIM * DIM + 255) / 256, 256>>>(Wq, Wk, Wv, Wo);

    gemm_mma<<<MB, 256, GSMEM>>>(dXh, dXl, dWth, dWtl, bq, bk, bv, dQ, dK, dV, 3, NNODES);

    attn_kernel<<<AB, 256>>>(att_bias, logits);

    gemm_mma<<<MB, 256, GSMEM>>>(dAh, dAl, dWth + 3 * DIM * DIM, dWtl + 3 * DIM * DIM,
                                 bo, nullptr, nullptr, out, nullptr, nullptr, 1, NNODES);
}

// round 6
// speedup vs baseline: 2.0301x; 1.0792x over previous
#include <cuda_runtime.h>
#include <cuda_bf16.h>
#include <cstdint>

#define NNODES 50000
#define EDGES  800000
#define DIM    128
#define HEADS  8
#define SCAN_B 256
#define NBLK   ((NNODES + SCAN_B - 1) / SCAN_B)   // 196

// ---------------- scratch (static device arrays; no allocs allowed) ----------------
__device__ int   g_is64;
__device__ int   g_dst[EDGES];
__device__ int   g_src[EDGES];
__device__ int   g_deg[NNODES];
__device__ int   g_rowoff[NNODES + 1];
__device__ int   g_cursor[NNODES];
__device__ int2  g_edge2[EDGES];        // (orig edge id, src node) in CSR order
__device__ int   g_blocksum[NBLK];
__device__ int   g_blockoff[NBLK];
__device__ float g_Q[(size_t)NNODES * DIM];
__device__ float g_K[(size_t)NNODES * DIM];
__device__ float g_V[(size_t)NNODES * DIM];
__device__ float g_agg[(size_t)NNODES * DIM];
__device__ __nv_bfloat16 g_Wth[4 * DIM * DIM];  // transposed [N][K] hi
__device__ __nv_bfloat16 g_Wtl[4 * DIM * DIM];  // transposed [N][K] lo

// ---------------- helpers ----------------
__device__ __forceinline__ uint32_t smem_u32(const void* p) {
    uint32_t a;
    asm("{ .reg .u64 t; cvta.to.shared.u64 t, %1; cvt.u32.u64 %0, t; }" : "=r"(a) : "l"(p));
    return a;
}
__device__ __forceinline__ void ldsm_x4(uint32_t* r, uint32_t addr) {
    asm volatile("ldmatrix.sync.aligned.m8n8.x4.shared.b16 {%0,%1,%2,%3}, [%4];"
                 : "=r"(r[0]), "=r"(r[1]), "=r"(r[2]), "=r"(r[3]) : "r"(addr));
}
__device__ __forceinline__ void mma16816(float* d, const uint32_t* a, const uint32_t* b) {
    asm volatile(
        "mma.sync.aligned.m16n8k16.row.col.f32.bf16.bf16.f32 "
        "{%0,%1,%2,%3}, {%4,%5,%6,%7}, {%8,%9}, {%0,%1,%2,%3};"
        : "+f"(d[0]), "+f"(d[1]), "+f"(d[2]), "+f"(d[3])
        : "r"(a[0]), "r"(a[1]), "r"(a[2]), "r"(a[3]), "r"(b[0]), "r"(b[1]));
}

// ---------------- edge index dtype detect ----------------
__global__ void detect_kernel(const void* ei) {
    if (blockIdx.x == 0 && threadIdx.x == 0) {
        const int* w = (const int*)ei;
        int is64 = 1;
        for (int i = 0; i < 64; i++) {
            int lo = w[2 * i], hi = w[2 * i + 1];
            if (hi != 0 || lo < 0 || lo >= NNODES) { is64 = 0; break; }
        }
        g_is64 = is64;
    }
}

__global__ void zero_deg_kernel() {
    int i = blockIdx.x * blockDim.x + threadIdx.x;
    if (i < NNODES) g_deg[i] = 0;
}

__global__ void convert_hist_kernel(const void* ei) {
    int i = blockIdx.x * blockDim.x + threadIdx.x;
    if (i >= EDGES) return;
    int d, s;
    if (g_is64) {
        const long long* p = (const long long*)ei;
        d = (int)p[i];
        s = (int)p[EDGES + i];
    } else {
        const int* p = (const int*)ei;
        d = p[i];
        s = p[EDGES + i];
    }
    g_dst[i] = d;
    g_src[i] = s;
    atomicAdd(&g_deg[d], 1);
}

// ---------------- parallel 3-phase exclusive scan of g_deg -> g_rowoff ----------------
__global__ void blocksum_kernel() {
    __shared__ int red[SCAN_B];
    int i = blockIdx.x * SCAN_B + threadIdx.x;
    int v = (i < NNODES) ? g_deg[i] : 0;
    red[threadIdx.x] = v;
    __syncthreads();
    #pragma unroll
    for (int off = SCAN_B / 2; off > 0; off >>= 1) {
        if (threadIdx.x < off) red[threadIdx.x] += red[threadIdx.x + off];
        __syncthreads();
    }
    if (threadIdx.x == 0) g_blocksum[blockIdx.x] = red[0];
}

__global__ void scanblock_kernel() {
    __shared__ int sc[SCAN_B];
    int tid = threadIdx.x;
    int v = (tid < NBLK) ? g_blocksum[tid] : 0;
    sc[tid] = v;
    __syncthreads();
    #pragma unroll
    for (int off = 1; off < SCAN_B; off <<= 1) {
        int u = (tid >= off) ? sc[tid - off] : 0;
        __syncthreads();
        sc[tid] += u;
        __syncthreads();
    }
    if (tid < NBLK) g_blockoff[tid] = sc[tid] - v;  // exclusive
    if (tid == NBLK - 1) g_rowoff[NNODES] = sc[tid];
}

__global__ void writeoff_kernel() {
    __shared__ int sc[SCAN_B];
    int tid = threadIdx.x;
    int i = blockIdx.x * SCAN_B + tid;
    int v = (i < NNODES) ? g_deg[i] : 0;
    sc[tid] = v;
    __syncthreads();
    #pragma unroll
    for (int off = 1; off < SCAN_B; off <<= 1) {
        int u = (tid >= off) ? sc[tid - off] : 0;
        __syncthreads();
        sc[tid] += u;
        __syncthreads();
    }
    if (i < NNODES) {
        int off = g_blockoff[blockIdx.x] + sc[tid] - v;  // exclusive
        g_rowoff[i] = off;
        g_cursor[i] = off;
    }
}

__global__ void scatter_kernel() {
    int i = blockIdx.x * blockDim.x + threadIdx.x;
    if (i >= EDGES) return;
    int d = g_dst[i];
    int p = atomicAdd(&g_cursor[d], 1);
    g_edge2[p] = make_int2(i, g_src[i]);
}

// ---------------- weight transpose + split ----------------
__global__ void conv_w_kernel(const float* __restrict__ W0, const float* __restrict__ W1,
                              const float* __restrict__ W2, const float* __restrict__ W3) {
    int i = blockIdx.x * blockDim.x + threadIdx.x;
    if (i >= 4 * DIM * DIM) return;
    int mat = i >> 14;
    int idx = i & 16383;
    int n = idx >> 7;
    int k = idx & 127;
    const float* W = (mat == 0) ? W0 : (mat == 1) ? W1 : (mat == 2) ? W2 : W3;
    float v = W[k * DIM + n];
    __nv_bfloat16 h = __float2bfloat16_rn(v);
    __nv_bfloat16 l = __float2bfloat16_rn(v - __bfloat162float(h));
    g_Wth[mat * DIM * DIM + idx] = h;
    g_Wtl[mat * DIM * DIM + idx] = l;
}

// ---------------- mma.sync split-bf16 GEMM (fp32 A converted inline) ----------------
#define LDA 136
#define SZ_TILE (128 * LDA * 2)
#define OFF_AH 0
#define OFF_AL SZ_TILE
#define OFF_BH (2 * SZ_TILE)
#define OFF_BL (3 * SZ_TILE)
#define GSMEM  (4 * SZ_TILE)

__global__ __launch_bounds__(256) void gemm_mma(
    const float* __restrict__ A,
    const __nv_bfloat16* __restrict__ Bh_all, const __nv_bfloat16* __restrict__ Bl_all,
    const float* __restrict__ bias0, const float* __restrict__ bias1,
    const float* __restrict__ bias2,
    float* __restrict__ C0, float* __restrict__ C1, float* __restrict__ C2,
    int count, int M) {
    extern __shared__ char sm[];
    const uint32_t sb = smem_u32(sm);
    const int tid = threadIdx.x, wid = tid >> 5, lane = tid & 31;
    const int bm = blockIdx.x * 128;

    // stage A: load fp32, split to (hi, lo) bf16 in registers
    #pragma unroll
    for (int it = 0; it < 16; ++it) {
        int g = tid + it * 256;
        int row = g >> 5;
        int col = (g & 31) << 2;
        int gr = bm + row;
        float4 v = make_float4(0.f, 0.f, 0.f, 0.f);
        if (gr < M) v = *(const float4*)(A + (size_t)gr * DIM + col);
        float a[4] = {v.x, v.y, v.z, v.w};
        __nv_bfloat16 h[4], l[4];
        #pragma unroll
        for (int u = 0; u < 4; u++) {
            h[u] = __float2bfloat16_rn(a[u]);
            l[u] = __float2bfloat16_rn(a[u] - __bfloat162float(h[u]));
        }
        *(unsigned long long*)(sm + OFF_AH + (row * LDA + col) * 2) = *(unsigned long long*)h;
        *(unsigned long long*)(sm + OFF_AL + (row * LDA + col) * 2) = *(unsigned long long*)l;
    }

    const int wm = wid & 3, wn = wid >> 2;
    const int m0 = wm * 32, n0 = wn * 64;
    const int g = lane >> 2, t = lane & 3;

    const int ar = lane & 15, ac = (lane >> 4) << 3;
    const int nn = (lane & 7) + ((lane >> 4) << 3);
    const int kkb = ((lane >> 3) & 1) << 3;

    for (int w = 0; w < count; w++) {
        const __nv_bfloat16* Bh = Bh_all + (size_t)w * DIM * DIM;
        const __nv_bfloat16* Bl = Bl_all + (size_t)w * DIM * DIM;
        const float* bias = (w == 0) ? bias0 : (w == 1) ? bias1 : bias2;
        float* C = (w == 0) ? C0 : (w == 1) ? C1 : C2;

        __syncthreads();
        #pragma unroll
        for (int it = 0; it < 16; ++it) {
            int gg = tid + it * 256;
            int row = gg >> 5;
            int col = (gg & 31) << 2;
            *(unsigned long long*)(sm + OFF_BH + (row * LDA + col) * 2) =
                *(const unsigned long long*)(Bh + row * DIM + col);
            *(unsigned long long*)(sm + OFF_BL + (row * LDA + col) * 2) =
                *(const unsigned long long*)(Bl + row * DIM + col);
        }
        __syncthreads();

        float acc[2][8][4];
        #pragma unroll
        for (int mt = 0; mt < 2; mt++)
            #pragma unroll
            for (int nt = 0; nt < 8; nt++)
                #pragma unroll
                for (int u = 0; u < 4; u++) acc[mt][nt][u] = 0.f;

        #pragma unroll
        for (int k = 0; k < 8; k++) {
            const int k0 = k * 16;
            uint32_t aH[2][4], aL[2][4], bH[4][4], bL[4][4];
            #pragma unroll
            for (int mt = 0; mt < 2; mt++) {
                uint32_t off = ((m0 + mt * 16 + ar) * LDA + k0 + ac) * 2;
                ldsm_x4(aH[mt], sb + OFF_AH + off);
                ldsm_x4(aL[mt], sb + OFF_AL + off);
            }
            #pragma unroll
            for (int nb = 0; nb < 4; nb++) {
                uint32_t off = ((n0 + nb * 16 + nn) * LDA + k0 + kkb) * 2;
                ldsm_x4(bH[nb], sb + OFF_BH + off);
                ldsm_x4(bL[nb], sb + OFF_BL + off);
            }
            #pragma unroll
            for (int mt = 0; mt < 2; mt++)
                #pragma unroll
                for (int nb = 0; nb < 4; nb++) {
                    mma16816(acc[mt][2 * nb],     aH[mt], bH[nb]);
                    mma16816(acc[mt][2 * nb],     aH[mt], bL[nb]);
                    mma16816(acc[mt][2 * nb],     aL[mt], bH[nb]);
                    mma16816(acc[mt][2 * nb + 1], aH[mt], bH[nb] + 2);
                    mma16816(acc[mt][2 * nb + 1], aH[mt], bL[nb] + 2);
                    mma16816(acc[mt][2 * nb + 1], aL[mt], bH[nb] + 2);
                }
        }

        #pragma unroll
        for (int mt = 0; mt < 2; mt++) {
            int r0 = bm + m0 + mt * 16 + g;
            #pragma unroll
            for (int nt = 0; nt < 8; nt++) {
                int col = n0 + nt * 8 + 2 * t;
                float bx = __ldg(bias + col), by = __ldg(bias + col + 1);
                if (r0 < M) {
                    float2 o = make_float2(acc[mt][nt][0] + bx, acc[mt][nt][1] + by);
                    *(float2*)(C + (size_t)r0 * DIM + col) = o;
                }
                if (r0 + 8 < M) {
                    float2 o = make_float2(acc[mt][nt][2] + bx, acc[mt][nt][3] + by);
                    *(float2*)(C + (size_t)(r0 + 8) * DIM + col) = o;
                }
            }
        }
    }
}

// ---------------- per-node edge attention (one warp per node) ----------------
__global__ __launch_bounds__(256) void attn_kernel(const float* __restrict__ att_bias,
                                                   float* __restrict__ logits_out) {
    int warp = (blockIdx.x * blockDim.x + threadIdx.x) >> 5;
    if (warp >= NNODES) return;
    const int lane = threadIdx.x & 31;
    const int n = warp;
    const int beg = g_rowoff[n];
    const int end = g_rowoff[n + 1];

    float4 q = *(const float4*)(g_Q + (size_t)n * DIM + lane * 4);
    const int head = lane >> 2;
    const float scale = 0.25f;

    float m = -__int_as_float(0x7f800000);
    float s = 0.f;
    float4 acc = make_float4(0.f, 0.f, 0.f, 0.f);

    int j = beg;
    int e = 0;
    float4 k4, v4;
    float ab = 0.f;
    if (j < end) {
        int2 es = g_edge2[j];
        e = es.x;
        k4 = *(const float4*)(g_K + (size_t)es.y * DIM + lane * 4);
        v4 = *(const float4*)(g_V + (size_t)es.y * DIM + lane * 4);
        ab = __ldg(att_bias + (size_t)e * HEADS + head);
    }
    while (j < end) {
        int jn = j + 1;
        int en = 0;
        float4 k4n, v4n;
        float abn = 0.f;
        if (jn < end) {
            int2 es = g_edge2[jn];
            en = es.x;
            k4n = *(const float4*)(g_K + (size_t)es.y * DIM + lane * 4);
            v4n = *(const float4*)(g_V + (size_t)es.y * DIM + lane * 4);
            abn = __ldg(att_bias + (size_t)en * HEADS + head);
        }
        float d = q.x * k4.x + q.y * k4.y + q.z * k4.z + q.w * k4.w;
        d += __shfl_xor_sync(0xffffffffu, d, 1);
        d += __shfl_xor_sync(0xffffffffu, d, 2);
        float logit = d * scale + ab;
        if ((lane & 3) == 0)
            logits_out[(size_t)e * HEADS + head] = logit;

        float nm = fmaxf(m, logit);
        float f = __expf(m - nm);
        float ex = __expf(logit - nm);
        s = s * f + ex;
        acc.x = acc.x * f + ex * v4.x;
        acc.y = acc.y * f + ex * v4.y;
        acc.z = acc.z * f + ex * v4.z;
        acc.w = acc.w * f + ex * v4.w;
        m = nm;

        j = jn; e = en; k4 = k4n; v4 = v4n; ab = abn;
    }
    float inv = (s > 0.f) ? (1.f / s) : 0.f;
    float4 o = make_float4(acc.x * inv, acc.y * inv, acc.z * inv, acc.w * inv);
    *(float4*)(g_agg + (size_t)n * DIM + lane * 4) = o;
}

// ---------------- launch ----------------
extern "C" void kernel_launch(void* const* d_in, const int* in_sizes, int n_in,
                              void* d_out, int out_size) {
    const float* x        = (const float*)d_in[0];
    const void*  ei       = d_in[1];
    const float* att_bias = (const float*)d_in[2];
    const float* Wq = (const float*)d_in[3];
    const float* bq = (const float*)d_in[4];
    const float* Wk = (const float*)d_in[5];
    const float* bk = (const float*)d_in[6];
    const float* Wv = (const float*)d_in[7];
    const float* bv = (const float*)d_in[8];
    const float* Wo = (const float*)d_in[9];
    const float* bo = (const float*)d_in[10];

    float* out = (float*)d_out;
    float* logits = out + (size_t)NNODES * DIM;

    float* dQ;   cudaGetSymbolAddress((void**)&dQ, g_Q);
    float* dK;   cudaGetSymbolAddress((void**)&dK, g_K);
    float* dV;   cudaGetSymbolAddress((void**)&dV, g_V);
    float* dAgg; cudaGetSymbolAddress((void**)&dAgg, g_agg);
    __nv_bfloat16* dWth; cudaGetSymbolAddress((void**)&dWth, g_Wth);
    __nv_bfloat16* dWtl; cudaGetSymbolAddress((void**)&dWtl, g_Wtl);

    cudaFuncSetAttribute(gemm_mma, cudaFuncAttributeMaxDynamicSharedMemorySize, GSMEM);

    const int EB = (EDGES + 255) / 256;
    const int NB = (NNODES + 255) / 256;
    const int MB = (NNODES + 127) / 128;
    const int AB = (NNODES * 32 + 255) / 256;

    detect_kernel<<<1, 32>>>(ei);
    zero_deg_kernel<<<NB, 256>>>();
    convert_hist_kernel<<<EB, 256>>>(ei);
    blocksum_kernel<<<NBLK, SCAN_B>>>();
    scanblock_kernel<<<1, SCAN_B>>>();
    writeoff_kernel<<<NBLK, SCAN_B>>>();
    scatter_kernel<<<EB, 256>>>();

    conv_w_kernel<<<(4 * DIM * DIM + 255) / 256, 256>>>(Wq, Wk, Wv, Wo);
    gemm_mma<<<MB, 256, GSMEM>>>(x, dWth, dWtl, bq, bk, bv, dQ, dK, dV, 3, NNODES);

    attn_kernel<<<AB, 256>>>(att_bias, logits);

    gemm_mma<<<MB, 256, GSMEM>>>(dAgg, dWth + 3 * DIM * DIM, dWtl + 3 * DIM * DIM,
                                 bo, nullptr, nullptr, out, nullptr, nullptr, 1, NNODES);
}

// round 10
// speedup vs baseline: 2.1532x; 1.0606x over previous
#include <cuda_runtime.h>
#include <cuda_bf16.h>
#include <cstdint>

#define NNODES 50000
#define EDGES  800000
#define DIM    128
#define HEADS  8
#define SCAN_B 256
#define NBLK   ((NNODES + SCAN_B - 1) / SCAN_B)   // 196

// ---------------- scratch (static device arrays; no allocs allowed) ----------------
__device__ int   g_is64;
__device__ int2  g_ds[EDGES];           // (dst, src) int32
__device__ int   g_deg[NNODES];
__device__ int   g_rowoff[NNODES + 1];
__device__ int   g_cursor[NNODES];
__device__ int2  g_edge2[EDGES];        // (orig edge id, src node) in CSR order
__device__ int   g_blocksum[NBLK];
__device__ int   g_blockoff[NBLK];
__device__ float g_Q[(size_t)NNODES * DIM];
__device__ float g_K[(size_t)NNODES * DIM];
__device__ float g_V[(size_t)NNODES * DIM];
__device__ float g_agg[(size_t)NNODES * DIM];
__device__ __nv_bfloat16 g_Wth[4 * DIM * DIM];  // transposed [N][K] hi
__device__ __nv_bfloat16 g_Wtl[4 * DIM * DIM];  // transposed [N][K] lo

// ---------------- helpers ----------------
__device__ __forceinline__ uint32_t smem_u32(const void* p) {
    uint32_t a;
    asm("{ .reg .u64 t; cvta.to.shared.u64 t, %1; cvt.u32.u64 %0, t; }" : "=r"(a) : "l"(p));
    return a;
}
__device__ __forceinline__ void ldsm_x4(uint32_t* r, uint32_t addr) {
    asm volatile("ldmatrix.sync.aligned.m8n8.x4.shared.b16 {%0,%1,%2,%3}, [%4];"
                 : "=r"(r[0]), "=r"(r[1]), "=r"(r[2]), "=r"(r[3]) : "r"(addr));
}
__device__ __forceinline__ void mma16816(float* d, const uint32_t* a, const uint32_t* b) {
    asm volatile(
        "mma.sync.aligned.m16n8k16.row.col.f32.bf16.bf16.f32 "
        "{%0,%1,%2,%3}, {%4,%5,%6,%7}, {%8,%9}, {%0,%1,%2,%3};"
        : "+f"(d[0]), "+f"(d[1]), "+f"(d[2]), "+f"(d[3])
        : "r"(a[0]), "r"(a[1]), "r"(a[2]), "r"(a[3]), "r"(b[0]), "r"(b[1]));
}

// ---------------- edge index dtype detect ----------------
__global__ void detect_kernel(const void* ei) {
    if (blockIdx.x == 0 && threadIdx.x == 0) {
        const int* w = (const int*)ei;
        int is64 = 1;
        for (int i = 0; i < 64; i++) {
            int lo = w[2 * i], hi = w[2 * i + 1];
            if (hi != 0 || lo < 0 || lo >= NNODES) { is64 = 0; break; }
        }
        g_is64 = is64;
    }
}

__global__ void zero_deg_kernel() {
    int i = blockIdx.x * blockDim.x + threadIdx.x;
    if (i < NNODES) g_deg[i] = 0;
}

__global__ void convert_hist_kernel(const void* ei) {
    int i = blockIdx.x * blockDim.x + threadIdx.x;
    if (i >= EDGES) return;
    int d, s;
    if (g_is64) {
        const long long* p = (const long long*)ei;
        d = (int)p[i];
        s = (int)p[EDGES + i];
    } else {
        const int* p = (const int*)ei;
        d = p[i];
        s = p[EDGES + i];
    }
    g_ds[i] = make_int2(d, s);
    atomicAdd(&g_deg[d], 1);
}

// ---------------- parallel 3-phase exclusive scan of g_deg -> g_rowoff ----------------
__global__ void blocksum_kernel() {
    __shared__ int red[SCAN_B];
    int i = blockIdx.x * SCAN_B + threadIdx.x;
    int v = (i < NNODES) ? g_deg[i] : 0;
    red[threadIdx.x] = v;
    __syncthreads();
    #pragma unroll
    for (int off = SCAN_B / 2; off > 0; off >>= 1) {
        if (threadIdx.x < off) red[threadIdx.x] += red[threadIdx.x + off];
        __syncthreads();
    }
    if (threadIdx.x == 0) g_blocksum[blockIdx.x] = red[0];
}

__global__ void scanblock_kernel() {
    __shared__ int sc[SCAN_B];
    int tid = threadIdx.x;
    int v = (tid < NBLK) ? g_blocksum[tid] : 0;
    sc[tid] = v;
    __syncthreads();
    #pragma unroll
    for (int off = 1; off < SCAN_B; off <<= 1) {
        int u = (tid >= off) ? sc[tid - off] : 0;
        __syncthreads();
        sc[tid] += u;
        __syncthreads();
    }
    if (tid < NBLK) g_blockoff[tid] = sc[tid] - v;  // exclusive
    if (tid == NBLK - 1) g_rowoff[NNODES] = sc[tid];
}

__global__ void writeoff_kernel() {
    __shared__ int sc[SCAN_B];
    int tid = threadIdx.x;
    int i = blockIdx.x * SCAN_B + tid;
    int v = (i < NNODES) ? g_deg[i] : 0;
    sc[tid] = v;
    __syncthreads();
    #pragma unroll
    for (int off = 1; off < SCAN_B; off <<= 1) {
        int u = (tid >= off) ? sc[tid - off] : 0;
        __syncthreads();
        sc[tid] += u;
        __syncthreads();
    }
    if (i < NNODES) {
        int off = g_blockoff[blockIdx.x] + sc[tid] - v;  // exclusive
        g_rowoff[i] = off;
        g_cursor[i] = off;
    }
}

__global__ void scatter_kernel() {
    int i = blockIdx.x * blockDim.x + threadIdx.x;
    if (i >= EDGES) return;
    int2 ds = g_ds[i];
    int p = atomicAdd(&g_cursor[ds.x], 1);
    g_edge2[p] = make_int2(i, ds.y);
}

// ---------------- weight transpose + split ----------------
__global__ void conv_w_kernel(const float* __restrict__ W0, const float* __restrict__ W1,
                              const float* __restrict__ W2, const float* __restrict__ W3) {
    int i = blockIdx.x * blockDim.x + threadIdx.x;
    if (i >= 4 * DIM * DIM) return;
    int mat = i >> 14;
    int idx = i & 16383;
    int n = idx >> 7;
    int k = idx & 127;
    const float* W = (mat == 0) ? W0 : (mat == 1) ? W1 : (mat == 2) ? W2 : W3;
    float v = W[k * DIM + n];
    __nv_bfloat16 h = __float2bfloat16_rn(v);
    __nv_bfloat16 l = __float2bfloat16_rn(v - __bfloat162float(h));
    g_Wth[mat * DIM * DIM + idx] = h;
    g_Wtl[mat * DIM * DIM + idx] = l;
}

// ---------------- mma.sync split-bf16 GEMM (fp32 A converted inline) ----------------
#define LDA 136
#define SZ_TILE (128 * LDA * 2)
#define OFF_AH 0
#define OFF_AL SZ_TILE
#define OFF_BH (2 * SZ_TILE)
#define OFF_BL (3 * SZ_TILE)
#define GSMEM  (4 * SZ_TILE)

__global__ __launch_bounds__(256) void gemm_mma(
    const float* __restrict__ A,
    const __nv_bfloat16* __restrict__ Bh_all, const __nv_bfloat16* __restrict__ Bl_all,
    const float* __restrict__ bias0, const float* __restrict__ bias1,
    const float* __restrict__ bias2,
    float* __restrict__ C0, float* __restrict__ C1, float* __restrict__ C2,
    int count, int M) {
    extern __shared__ char sm[];
    const uint32_t sb = smem_u32(sm);
    const int tid = threadIdx.x, wid = tid >> 5, lane = tid & 31;
    const int bm = blockIdx.x * 128;

    // stage A: load fp32, split to (hi, lo) bf16 in registers
    #pragma unroll
    for (int it = 0; it < 16; ++it) {
        int g = tid + it * 256;
        int row = g >> 5;
        int col = (g & 31) << 2;
        int gr = bm + row;
        float4 v = make_float4(0.f, 0.f, 0.f, 0.f);
        if (gr < M) v = *(const float4*)(A + (size_t)gr * DIM + col);
        float a[4] = {v.x, v.y, v.z, v.w};
        __nv_bfloat16 h[4], l[4];
        #pragma unroll
        for (int u = 0; u < 4; u++) {
            h[u] = __float2bfloat16_rn(a[u]);
            l[u] = __float2bfloat16_rn(a[u] - __bfloat162float(h[u]));
        }
        *(unsigned long long*)(sm + OFF_AH + (row * LDA + col) * 2) = *(unsigned long long*)h;
        *(unsigned long long*)(sm + OFF_AL + (row * LDA + col) * 2) = *(unsigned long long*)l;
    }

    const int wm = wid & 3, wn = wid >> 2;
    const int m0 = wm * 32, n0 = wn * 64;
    const int g = lane >> 2, t = lane & 3;

    const int ar = lane & 15, ac = (lane >> 4) << 3;
    const int nn = (lane & 7) + ((lane >> 4) << 3);
    const int kkb = ((lane >> 3) & 1) << 3;

    for (int w = 0; w < count; w++) {
        const __nv_bfloat16* Bh = Bh_all + (size_t)w * DIM * DIM;
        const __nv_bfloat16* Bl = Bl_all + (size_t)w * DIM * DIM;
        const float* bias = (w == 0) ? bias0 : (w == 1) ? bias1 : bias2;
        float* C = (w == 0) ? C0 : (w == 1) ? C1 : C2;

        __syncthreads();
        #pragma unroll
        for (int it = 0; it < 16; ++it) {
            int gg = tid + it * 256;
            int row = gg >> 5;
            int col = (gg & 31) << 2;
            *(unsigned long long*)(sm + OFF_BH + (row * LDA + col) * 2) =
                *(const unsigned long long*)(Bh + row * DIM + col);
            *(unsigned long long*)(sm + OFF_BL + (row * LDA + col) * 2) =
                *(const unsigned long long*)(Bl + row * DIM + col);
        }
        __syncthreads();

        float acc[2][8][4];
        #pragma unroll
        for (int mt = 0; mt < 2; mt++)
            #pragma unroll
            for (int nt = 0; nt < 8; nt++)
                #pragma unroll
                for (int u = 0; u < 4; u++) acc[mt][nt][u] = 0.f;

        #pragma unroll
        for (int k = 0; k < 8; k++) {
            const int k0 = k * 16;
            uint32_t aH[2][4], aL[2][4], bH[4][4], bL[4][4];
            #pragma unroll
            for (int mt = 0; mt < 2; mt++) {
                uint32_t off = ((m0 + mt * 16 + ar) * LDA + k0 + ac) * 2;
                ldsm_x4(aH[mt], sb + OFF_AH + off);
                ldsm_x4(aL[mt], sb + OFF_AL + off);
            }
            #pragma unroll
            for (int nb = 0; nb < 4; nb++) {
                uint32_t off = ((n0 + nb * 16 + nn) * LDA + k0 + kkb) * 2;
                ldsm_x4(bH[nb], sb + OFF_BH + off);
                ldsm_x4(bL[nb], sb + OFF_BL + off);
            }
            #pragma unroll
            for (int mt = 0; mt < 2; mt++)
                #pragma unroll
                for (int nb = 0; nb < 4; nb++) {
                    mma16816(acc[mt][2 * nb],     aH[mt], bH[nb]);
                    mma16816(acc[mt][2 * nb],     aH[mt], bL[nb]);
                    mma16816(acc[mt][2 * nb],     aL[mt], bH[nb]);
                    mma16816(acc[mt][2 * nb + 1], aH[mt], bH[nb] + 2);
                    mma16816(acc[mt][2 * nb + 1], aH[mt], bL[nb] + 2);
                    mma16816(acc[mt][2 * nb + 1], aL[mt], bH[nb] + 2);
                }
        }

        #pragma unroll
        for (int mt = 0; mt < 2; mt++) {
            int r0 = bm + m0 + mt * 16 + g;
            #pragma unroll
            for (int nt = 0; nt < 8; nt++) {
                int col = n0 + nt * 8 + 2 * t;
                float bx = __ldg(bias + col), by = __ldg(bias + col + 1);
                if (r0 < M) {
                    float2 o = make_float2(acc[mt][nt][0] + bx, acc[mt][nt][1] + by);
                    *(float2*)(C + (size_t)r0 * DIM + col) = o;
                }
                if (r0 + 8 < M) {
                    float2 o = make_float2(acc[mt][nt][2] + bx, acc[mt][nt][3] + by);
                    *(float2*)(C + (size_t)(r0 + 8) * DIM + col) = o;
                }
            }
        }
    }
}

// ---------------- per-node edge attention (one warp per node, unroll x2) ----------------
__global__ __launch_bounds__(256) void attn_kernel(const float* __restrict__ att_bias,
                                                   float* __restrict__ logits_out) {
    int warp = (blockIdx.x * blockDim.x + threadIdx.x) >> 5;
    if (warp >= NNODES) return;
    const int lane = threadIdx.x & 31;
    const int n = warp;
    const int beg = g_rowoff[n];
    const int end = g_rowoff[n + 1];

    float4 q = *(const float4*)(g_Q + (size_t)n * DIM + lane * 4);
    const int head = lane >> 2;
    const float scale = 0.25f;

    float m = -__int_as_float(0x7f800000);
    float s = 0.f;
    float4 acc = make_float4(0.f, 0.f, 0.f, 0.f);

    int j = beg;
    // main loop: two edges per iteration -> 4 wide loads in flight
    for (; j + 1 < end; j += 2) {
        int2 ea = g_edge2[j];
        int2 eb = g_edge2[j + 1];
        float4 ka = *(const float4*)(g_K + (size_t)ea.y * DIM + lane * 4);
        float4 va = *(const float4*)(g_V + (size_t)ea.y * DIM + lane * 4);
        float4 kb = *(const float4*)(g_K + (size_t)eb.y * DIM + lane * 4);
        float4 vb = *(const float4*)(g_V + (size_t)eb.y * DIM + lane * 4);
        float aba = __ldcs(att_bias + (size_t)ea.x * HEADS + head);
        float abb = __ldcs(att_bias + (size_t)eb.x * HEADS + head);

        float da = q.x * ka.x + q.y * ka.y + q.z * ka.z + q.w * ka.w;
        float db = q.x * kb.x + q.y * kb.y + q.z * kb.z + q.w * kb.w;
        da += __shfl_xor_sync(0xffffffffu, da, 1);
        db += __shfl_xor_sync(0xffffffffu, db, 1);
        da += __shfl_xor_sync(0xffffffffu, da, 2);
        db += __shfl_xor_sync(0xffffffffu, db, 2);
        float la = da * scale + aba;
        float lb = db * scale + abb;
        if ((lane & 3) == 0) {
            __stcs(logits_out + (size_t)ea.x * HEADS + head, la);
            __stcs(logits_out + (size_t)eb.x * HEADS + head, lb);
        }

        float nm = fmaxf(m, la);
        float f = __expf(m - nm);
        float ex = __expf(la - nm);
        s = s * f + ex;
        acc.x = acc.x * f + ex * va.x;
        acc.y = acc.y * f + ex * va.y;
        acc.z = acc.z * f + ex * va.z;
        acc.w = acc.w * f + ex * va.w;
        m = nm;

        nm = fmaxf(m, lb);
        f = __expf(m - nm);
        ex = __expf(lb - nm);
        s = s * f + ex;
        acc.x = acc.x * f + ex * vb.x;
        acc.y = acc.y * f + ex * vb.y;
        acc.z = acc.z * f + ex * vb.z;
        acc.w = acc.w * f + ex * vb.w;
        m = nm;
    }
    if (j < end) {
        int2 ea = g_edge2[j];
        float4 ka = *(const float4*)(g_K + (size_t)ea.y * DIM + lane * 4);
        float4 va = *(const float4*)(g_V + (size_t)ea.y * DIM + lane * 4);
        float aba = __ldcs(att_bias + (size_t)ea.x * HEADS + head);

        float da = q.x * ka.x + q.y * ka.y + q.z * ka.z + q.w * ka.w;
        da += __shfl_xor_sync(0xffffffffu, da, 1);
        da += __shfl_xor_sync(0xffffffffu, da, 2);
        float la = da * scale + aba;
        if ((lane & 3) == 0)
            __stcs(logits_out + (size_t)ea.x * HEADS + head, la);

        float nm = fmaxf(m, la);
        float f = __expf(m - nm);
        float ex = __expf(la - nm);
        s = s * f + ex;
        acc.x = acc.x * f + ex * va.x;
        acc.y = acc.y * f + ex * va.y;
        acc.z = acc.z * f + ex * va.z;
        acc.w = acc.w * f + ex * va.w;
        m = nm;
    }
    float inv = (s > 0.f) ? (1.f / s) : 0.f;
    float4 o = make_float4(acc.x * inv, acc.y * inv, acc.z * inv, acc.w * inv);
    __stcs((float4*)(g_agg + (size_t)n * DIM + lane * 4), o);
}

// ---------------- launch ----------------
extern "C" void kernel_launch(void* const* d_in, const int* in_sizes, int n_in,
                              void* d_out, int out_size) {
    const float* x        = (const float*)d_in[0];
    const void*  ei       = d_in[1];
    const float* att_bias = (const float*)d_in[2];
    const float* Wq = (const float*)d_in[3];
    const float* bq = (const float*)d_in[4];
    const float* Wk = (const float*)d_in[5];
    const float* bk = (const float*)d_in[6];
    const float* Wv = (const float*)d_in[7];
    const float* bv = (const float*)d_in[8];
    const float* Wo = (const float*)d_in[9];
    const float* bo = (const float*)d_in[10];

    float* out = (float*)d_out;
    float* logits = out + (size_t)NNODES * DIM;

    float* dQ;   cudaGetSymbolAddress((void**)&dQ, g_Q);
    float* dK;   cudaGetSymbolAddress((void**)&dK, g_K);
    float* dV;   cudaGetSymbolAddress((void**)&dV, g_V);
    float* dAgg; cudaGetSymbolAddress((void**)&dAgg, g_agg);
    __nv_bfloat16* dWth; cudaGetSymbolAddress((void**)&dWth, g_Wth);
    __nv_bfloat16* dWtl; cudaGetSymbolAddress((void**)&dWtl, g_Wtl);

    cudaFuncSetAttribute(gemm_mma, cudaFuncAttributeMaxDynamicSharedMemorySize, GSMEM);

    const int EB = (EDGES + 255) / 256;
    const int NB = (NNODES + 255) / 256;
    const int MB = (NNODES + 127) / 128;
    const int AB = (NNODES * 32 + 255) / 256;

    detect_kernel<<<1, 32>>>(ei);
    zero_deg_kernel<<<NB, 256>>>();
    convert_hist_kernel<<<EB, 256>>>(ei);
    blocksum_kernel<<<NBLK, SCAN_B>>>();
    scanblock_kernel<<<1, SCAN_B>>>();
    writeoff_kernel<<<NBLK, SCAN_B>>>();
    scatter_kernel<<<EB, 256>>>();

    conv_w_kernel<<<(4 * DIM * DIM + 255) / 256, 256>>>(Wq, Wk, Wv, Wo);
    gemm_mma<<<MB, 256, GSMEM>>>(x, dWth, dWtl, bq, bk, bv, dQ, dK, dV, 3, NNODES);

    attn_kernel<<<AB, 256>>>(att_bias, logits);

    gemm_mma<<<MB, 256, GSMEM>>>(dAgg, dWth + 3 * DIM * DIM, dWtl + 3 * DIM * DIM,
                                 bo, nullptr, nullptr, out, nullptr, nullptr, 1, NNODES);
}